// round 10
// baseline (speedup 1.0000x reference)
#include <cuda_runtime.h>
#include <cuda_bf16.h>
#include <cstdint>

// ---------------------------------------------------------------------------
// BinaryTreeLSTM  (B=64, L=2048, H=DW=128, V=100000) — mma.sync split-bf16
//
// Phase 1:  h0 = emb[word_ids] @ W_wh        (M=131072, K=128, N=128)
// Tree:     s = (hl+hr) @ W_hh + 2*b_hh      (M=pairs,  K=128, N=640) ; gates
//
// Split-bf16: x = x_hi + x_lo, W = W_hi + W_lo
//   s ~= x_hi@W_hi + x_hi@W_lo + x_lo@W_hi   (3 bf16 passes, fp32 accum)
// W_hh column-reordered: tile tt (N=160) = cols tt*32..+31 of ALL 5 gates.
// R9: R8 + DOUBLE-BUFFERED pre-split x (fixes the cross-CTA WAR race where a
// CTA's epilogue write of next-level x overlapped another CTA's staging read
// of current-level x in the same buffer).
// ---------------------------------------------------------------------------

#define BB 64
#define LL 2048
#define HH 128
#define MAXP (BB * LL / 2)

__device__ float g_h0[BB * LL * HH];             // 67 MB
__device__ float g_h1[MAXP * HH];                // 33.5 MB
__device__ __nv_bfloat16 g_xhi0[MAXP * HH];      // x ping-pong buffers
__device__ __nv_bfloat16 g_xlo0[MAXP * HH];
__device__ __nv_bfloat16 g_xhi1[MAXP * HH / 2];
__device__ __nv_bfloat16 g_xlo1[MAXP * HH / 2];
__device__ __nv_bfloat16 g_WrHi[4 * 160 * 128];  // reordered W_hh^T hi
__device__ __nv_bfloat16 g_WrLo[4 * 160 * 128];  // reordered W_hh^T lo
__device__ __nv_bfloat16 g_WtHi[128 * 128];      // W_wh^T hi
__device__ __nv_bfloat16 g_WtLo[128 * 128];      // W_wh^T lo

// ---------------------------------------------------------------- helpers
static __device__ __forceinline__ uint32_t smem_u32(const void* p) {
    uint32_t a;
    asm("{ .reg .u64 t; cvta.to.shared.u64 t, %1; cvt.u32.u64 %0, t; }"
        : "=r"(a) : "l"(p));
    return a;
}
// XOR-swizzled byte offset: rows of 256B, 16B chunks permuted by (row&7)
static __device__ __forceinline__ uint32_t swz(int row, int kb) {
    return (uint32_t)(row * 256 + (kb ^ ((row & 7) << 4)));
}
static __device__ __forceinline__ void ldmx4(uint32_t* r, uint32_t a) {
    asm volatile("ldmatrix.sync.aligned.m8n8.x4.shared.b16 {%0,%1,%2,%3}, [%4];"
                 : "=r"(r[0]), "=r"(r[1]), "=r"(r[2]), "=r"(r[3]) : "r"(a));
}
static __device__ __forceinline__ void ldmx2(uint32_t* r, uint32_t a) {
    asm volatile("ldmatrix.sync.aligned.m8n8.x2.shared.b16 {%0,%1}, [%2];"
                 : "=r"(r[0]), "=r"(r[1]) : "r"(a));
}
static __device__ __forceinline__ void mma_bf16(float* d, const uint32_t* a,
                                                const uint32_t* b) {
    asm volatile(
        "mma.sync.aligned.m16n8k16.row.col.f32.bf16.bf16.f32 "
        "{%0,%1,%2,%3}, {%4,%5,%6,%7}, {%8,%9}, {%0,%1,%2,%3};"
        : "+f"(d[0]), "+f"(d[1]), "+f"(d[2]), "+f"(d[3])
        : "r"(a[0]), "r"(a[1]), "r"(a[2]), "r"(a[3]), "r"(b[0]), "r"(b[1]));
}
static __device__ __forceinline__ void split_bf16(float x, unsigned short& h,
                                                  unsigned short& l) {
    __nv_bfloat16 hi = __float2bfloat16(x);
    __nv_bfloat16 lo = __float2bfloat16(x - __bfloat162float(hi));
    h = __bfloat16_as_ushort(hi);
    l = __bfloat16_as_ushort(lo);
}
static __device__ __forceinline__ float sg(float x) {
    return __fdividef(1.0f, 1.0f + __expf(-x));
}
static __device__ __forceinline__ float th(float x) {
    return __fdividef(2.0f, 1.0f + __expf(-2.0f * x)) - 1.0f;
}

// ---------------------------------------------------------------- weight prep
__global__ void prep_weights(const float* __restrict__ Whh,
                             const float* __restrict__ Wwh) {
    int idx = blockIdx.x * 256 + threadIdx.x;
    if (idx < 4 * 160 * 128) {
        int tt = idx / (160 * 128);
        int rem = idx - tt * 160 * 128;
        int row = rem >> 7, k = rem & 127;     // row = g*32+cc
        int g = row >> 5, cc = row & 31;
        float w = Whh[(size_t)k * 640 + g * 128 + tt * 32 + cc];
        unsigned short h, l; split_bf16(w, h, l);
        g_WrHi[idx] = __ushort_as_bfloat16(h);
        g_WrLo[idx] = __ushort_as_bfloat16(l);
    } else if (idx < 4 * 160 * 128 + 128 * 128) {
        int j = idx - 4 * 160 * 128;
        int n = j >> 7, k = j & 127;
        float w = Wwh[(size_t)k * 128 + n];
        unsigned short h, l; split_bf16(w, h, l);
        g_WtHi[j] = __ushort_as_bfloat16(h);
        g_WtLo[j] = __ushort_as_bfloat16(l);
    }
}

// ---------------------------------------------------------------- tree GEMM
// 512 threads, 16 warps as 4(M) x 4(N); warp tile 32 rows x 40 cols.
// smem: Xhi 32KB | Xlo 32KB | Whi 40KB | Wlo 40KB = 144KB; S reuses (82KB)
#define TS_XHI 0
#define TS_XLO 32768
#define TS_WHI 65536
#define TS_WLO (65536 + 40960)
#define TS_TOTAL (65536 + 81920)
#define SST 164   // S row stride in floats (164 % 32 == 4: conflict-free)

__global__ void __launch_bounds__(512)
tree_mma(const float* __restrict__ hin, float* __restrict__ hout,
         const float* __restrict__ bhh,
         const __nv_bfloat16* __restrict__ xin_hi,
         const __nv_bfloat16* __restrict__ xin_lo,
         __nv_bfloat16* __restrict__ xout_hi,
         __nv_bfloat16* __restrict__ xout_lo,
         int P, int writeX)
{
    extern __shared__ char smem[];
    const uint32_t sb = smem_u32(smem);
    const int t = threadIdx.x, wid = t >> 5, lane = t & 31;
    const int Mbase = blockIdx.x * 128;
    const int tt = blockIdx.y;

    // stage W tile (160 x 128 bf16, hi+lo)
    {
        const uint4* sH = (const uint4*)(g_WrHi + tt * 160 * 128);
        const uint4* sL = (const uint4*)(g_WrLo + tt * 160 * 128);
        #pragma unroll
        for (int i = t; i < 2560; i += 512) {
            int row = i >> 4;
            uint32_t off = swz(row, (i & 15) << 4);
            *(uint4*)(smem + TS_WHI + off) = sH[i];
            *(uint4*)(smem + TS_WLO + off) = sL[i];
        }
    }
    // stage X tile: pre-split bf16 hi/lo straight from global
    {
        #pragma unroll
        for (int i = t; i < 2048; i += 512) {
            int row = i >> 4;
            size_t gi = (size_t)(Mbase + row) * 16 + (i & 15);
            uint4 vh = ((const uint4*)xin_hi)[gi];
            uint4 vl = ((const uint4*)xin_lo)[gi];
            uint32_t off = swz(row, (i & 15) << 4);
            *(uint4*)(smem + TS_XHI + off) = vh;
            *(uint4*)(smem + TS_XLO + off) = vl;
        }
    }
    __syncthreads();

    // warp tile: (wid>>2) of 4 M-tiles (32 rows), (wid&3) of 4 N-tiles (40 cols)
    const int mw = (wid >> 2) * 32, nw = (wid & 3) * 40;
    float acc[2][5][4];
    #pragma unroll
    for (int mi = 0; mi < 2; mi++)
        #pragma unroll
        for (int nj = 0; nj < 5; nj++)
            #pragma unroll
            for (int r = 0; r < 4; r++) acc[mi][nj][r] = 0.0f;

    const int la = lane & 15;
    const int arow_off = mw + la;          // + mi*16
    const int akb_off = (lane >> 4) * 16;  // + kstep*32
    // paired-B x4 mapping: matrices [nj k0, nj k1, nj+1 k0, nj+1 k1]
    const int b4row = nw + ((lane >> 4) & 1) * 8 + (lane & 7);
    const int b4kb = ((lane >> 3) & 1) * 16;
    // single-B x2 mapping (nj = 4)
    const int b2row = nw + 32 + (la & 7);
    const int b2kb = (la >> 3) * 16;

    #pragma unroll
    for (int ks = 0; ks < 8; ks++) {
        uint32_t ah[2][4], al[2][4];
        #pragma unroll
        for (int mi = 0; mi < 2; mi++) {
            int row = arow_off + mi * 16;
            uint32_t off = swz(row, akb_off + ks * 32);
            ldmx4(ah[mi], sb + TS_XHI + off);
            ldmx4(al[mi], sb + TS_XLO + off);
        }
        uint32_t bh[10], bl[10];   // [nj*2 + khalf]
        #pragma unroll
        for (int njp = 0; njp < 2; njp++) {
            uint32_t off = swz(b4row + njp * 16, b4kb + ks * 32);
            ldmx4(bh + njp * 4, sb + TS_WHI + off);
            ldmx4(bl + njp * 4, sb + TS_WLO + off);
        }
        {
            uint32_t off = swz(b2row, b2kb + ks * 32);
            ldmx2(bh + 8, sb + TS_WHI + off);
            ldmx2(bl + 8, sb + TS_WLO + off);
        }
        #pragma unroll
        for (int nj = 0; nj < 5; nj++) {
            #pragma unroll
            for (int mi = 0; mi < 2; mi++) {
                mma_bf16(acc[mi][nj], ah[mi], bh + nj * 2);   // hi*hi
                mma_bf16(acc[mi][nj], ah[mi], bl + nj * 2);   // hi*lo
                mma_bf16(acc[mi][nj], al[mi], bh + nj * 2);   // lo*hi
            }
        }
    }
    __syncthreads();   // staging no longer needed; reuse smem for S

    // scatter S (rows 128 x cols 160, fp32) to smem
    float* S = (float*)smem;
    {
        const int r0 = mw + (lane >> 2);
        const int c0 = nw + (lane & 3) * 2;
        #pragma unroll
        for (int mi = 0; mi < 2; mi++)
            #pragma unroll
            for (int nj = 0; nj < 5; nj++) {
                int row = r0 + mi * 16, col = c0 + nj * 8;
                *(float2*)&S[row * SST + col] =
                    make_float2(acc[mi][nj][0], acc[mi][nj][1]);
                *(float2*)&S[(row + 8) * SST + col] =
                    make_float2(acc[mi][nj][2], acc[mi][nj][3]);
            }
    }
    __syncthreads();

    // fused gate epilogue: thread -> col cc=lane, rows wid*8..+7 (4 pairs)
    {
        const int cb = tt * 32;
        const int cc = lane;
        float b0 = 2.0f * bhh[0 * HH + cb + cc];
        float b1 = 2.0f * bhh[1 * HH + cb + cc];
        float b2 = 2.0f * bhh[2 * HH + cb + cc];
        float b3 = 2.0f * bhh[3 * HH + cb + cc];
        float b4 = 2.0f * bhh[4 * HH + cb + cc];
        #pragma unroll
        for (int rr = 0; rr < 8; rr += 2) {
            float hv[2];
            #pragma unroll
            for (int e = 0; e < 2; e++) {
                int row = wid * 8 + rr + e;
                int p = Mbase + row;
                const float* Sr = S + row * SST + cc;
                float ig = sg(Sr[0]   + b0);
                float lf = sg(Sr[32]  + b1);
                float rf = sg(Sr[64]  + b2);
                float og = sg(Sr[96]  + b3);
                float gg = th(Sr[128] + b4);
                float hl = hin[(size_t)(2 * p) * HH + cb + cc];
                float hr = hin[(size_t)(2 * p) * HH + HH + cb + cc];
                float c = ig * gg + lf * hl + rf * hr;
                hv[e] = og * th(c);
                hout[(size_t)p * HH + cb + cc] = hv[e];
            }
            if (writeX) {   // pre-split next level's x into the OTHER buffer
                unsigned short xh, xl;
                split_bf16(hv[0] + hv[1], xh, xl);
                size_t p2 = (size_t)((Mbase + wid * 8 + rr) >> 1) * HH + cb + cc;
                xout_hi[p2] = __ushort_as_bfloat16(xh);
                xout_lo[p2] = __ushort_as_bfloat16(xl);
            }
        }
    }
}

// ---------------------------------------------------------------- embed GEMM
// 512 threads, 16 warps as 4(M) x 4(N); warp tile 32 rows x 32 cols.
// smem: Xhi 32KB | Xlo 32KB | Whi 32KB | Wlo 32KB = 128KB; S reuses (66KB)
#define ES_XHI 0
#define ES_XLO 32768
#define ES_WHI 65536
#define ES_WLO 98304
#define ES_TOTAL 131072
#define EST 132   // S row stride (132 % 32 == 4)

__global__ void __launch_bounds__(512)
embed_mma(const int* __restrict__ wids_g, const float* __restrict__ emb,
          float* __restrict__ hout)
{
    extern __shared__ char smem[];
    __shared__ int wids_s[128];
    const uint32_t sb = smem_u32(smem);
    const int t = threadIdx.x, wid = t >> 5, lane = t & 31;
    const int Mbase = blockIdx.x * 128;

    if (t < 128) wids_s[t] = wids_g[Mbase + t];

    // stage W (128 x 128 bf16, hi+lo)
    {
        const uint4* sH = (const uint4*)g_WtHi;
        const uint4* sL = (const uint4*)g_WtLo;
        #pragma unroll
        for (int i = t; i < 2048; i += 512) {
            int row = i >> 4;
            uint32_t off = swz(row, (i & 15) << 4);
            *(uint4*)(smem + ES_WHI + off) = sH[i];
            *(uint4*)(smem + ES_WLO + off) = sL[i];
        }
    }
    __syncthreads();   // wids_s ready

    // gather + split E rows
    {
        #pragma unroll
        for (int i = t; i < 2048; i += 512) {
            int row = i >> 4, kc = (i & 15) * 8;      // 8 floats
            const float4* e4 =
                (const float4*)(emb + (size_t)wids_s[row] * 128 + kc);
            float4 a = e4[0], b = e4[1];
            ushort4 vh0, vl0, vh1, vl1;
            split_bf16(a.x, vh0.x, vl0.x); split_bf16(a.y, vh0.y, vl0.y);
            split_bf16(a.z, vh0.z, vl0.z); split_bf16(a.w, vh0.w, vl0.w);
            split_bf16(b.x, vh1.x, vl1.x); split_bf16(b.y, vh1.y, vl1.y);
            split_bf16(b.z, vh1.z, vl1.z); split_bf16(b.w, vh1.w, vl1.w);
            uint32_t off = swz(row, (i & 15) << 4);
            *(ushort4*)(smem + ES_XHI + off) = vh0;
            *(ushort4*)(smem + ES_XHI + off + 8) = vh1;
            *(ushort4*)(smem + ES_XLO + off) = vl0;
            *(ushort4*)(smem + ES_XLO + off + 8) = vl1;
        }
    }
    __syncthreads();

    // warp tile: (wid>>2) of 4 M-tiles (32 rows), (wid&3) of 4 N-tiles (32 cols)
    const int mw = (wid >> 2) * 32, nw = (wid & 3) * 32;
    float acc[2][4][4];
    #pragma unroll
    for (int mi = 0; mi < 2; mi++)
        #pragma unroll
        for (int nj = 0; nj < 4; nj++)
            #pragma unroll
            for (int r = 0; r < 4; r++) acc[mi][nj][r] = 0.0f;

    const int la = lane & 15;
    const int arow_off = mw + la;
    const int akb_off = (lane >> 4) * 16;
    const int b4row = nw + ((lane >> 4) & 1) * 8 + (lane & 7);
    const int b4kb = ((lane >> 3) & 1) * 16;

    #pragma unroll
    for (int ks = 0; ks < 8; ks++) {
        uint32_t ah[2][4], al[2][4];
        #pragma unroll
        for (int mi = 0; mi < 2; mi++) {
            int row = arow_off + mi * 16;
            uint32_t off = swz(row, akb_off + ks * 32);
            ldmx4(ah[mi], sb + ES_XHI + off);
            ldmx4(al[mi], sb + ES_XLO + off);
        }
        uint32_t bh[8], bl[8];
        #pragma unroll
        for (int njp = 0; njp < 2; njp++) {
            uint32_t off = swz(b4row + njp * 16, b4kb + ks * 32);
            ldmx4(bh + njp * 4, sb + ES_WHI + off);
            ldmx4(bl + njp * 4, sb + ES_WLO + off);
        }
        #pragma unroll
        for (int nj = 0; nj < 4; nj++) {
            #pragma unroll
            for (int mi = 0; mi < 2; mi++) {
                mma_bf16(acc[mi][nj], ah[mi], bh + nj * 2);
                mma_bf16(acc[mi][nj], ah[mi], bl + nj * 2);
                mma_bf16(acc[mi][nj], al[mi], bh + nj * 2);
            }
        }
    }
    __syncthreads();

    // S -> smem
    float* S = (float*)smem;
    {
        const int r0 = mw + (lane >> 2);
        const int c0 = nw + (lane & 3) * 2;
        #pragma unroll
        for (int mi = 0; mi < 2; mi++)
            #pragma unroll
            for (int nj = 0; nj < 4; nj++) {
                int row = r0 + mi * 16, col = c0 + nj * 8;
                *(float2*)&S[row * EST + col] =
                    make_float2(acc[mi][nj][0], acc[mi][nj][1]);
                *(float2*)&S[(row + 8) * EST + col] =
                    make_float2(acc[mi][nj][2], acc[mi][nj][3]);
            }
    }
    __syncthreads();
    // coalesced h0 stores
    {
        #pragma unroll
        for (int i = t; i < 4096; i += 512) {       // 128 rows x 32 float4
            int row = i >> 5, c4 = i & 31;
            float4 v = *(const float4*)&S[row * EST + c4 * 4];
            ((float4*)hout)[(size_t)(Mbase + row) * 32 + c4] = v;
        }
    }
    // pre-split level-0 x into buffer 0: pairs are tile-internal
    {
        #pragma unroll
        for (int i = t; i < 1024; i += 512) {       // 64 pair-rows x 16 chunks
            int r2 = i >> 4, ch = i & 15;
            const float* s0 = &S[(2 * r2) * EST + ch * 8];
            const float* s1 = &S[(2 * r2 + 1) * EST + ch * 8];
            ushort4 vh0, vl0, vh1, vl1;
            split_bf16(s0[0] + s1[0], vh0.x, vl0.x);
            split_bf16(s0[1] + s1[1], vh0.y, vl0.y);
            split_bf16(s0[2] + s1[2], vh0.z, vl0.z);
            split_bf16(s0[3] + s1[3], vh0.w, vl0.w);
            split_bf16(s0[4] + s1[4], vh1.x, vl1.x);
            split_bf16(s0[5] + s1[5], vh1.y, vl1.y);
            split_bf16(s0[6] + s1[6], vh1.z, vl1.z);
            split_bf16(s0[7] + s1[7], vh1.w, vl1.w);
            size_t eb = (size_t)((Mbase >> 1) + r2) * HH + ch * 8;
            *(ushort4*)(g_xhi0 + eb) = vh0;
            *(ushort4*)(g_xhi0 + eb + 4) = vh1;
            *(ushort4*)(g_xlo0 + eb) = vl0;
            *(ushort4*)(g_xlo0 + eb + 4) = vl1;
        }
    }
}

// ---------------------------------------------------------------- tail levels
// Fused n=16,8,4,2: one CTA per batch element, h state in smem, fp32 FFMA.
__global__ void __launch_bounds__(256)
tree_tail(const float* __restrict__ hin, float* __restrict__ out,
          const float* __restrict__ Whh, const float* __restrict__ bhh)
{
    __shared__ float h[16][128];
    __shared__ float xb[8][128];
    __shared__ float sbuf[8][640];
    const int b = blockIdx.x, t = threadIdx.x;

    for (int i = t; i < 16 * 128; i += 256)
        h[i >> 7][i & 127] = hin[(size_t)b * 16 * 128 + i];
    __syncthreads();

    for (int n = 16; n > 1; n >>= 1) {
        const int hf = n >> 1;
        for (int i = t; i < hf * 128; i += 256) {
            int p = i >> 7, c = i & 127;
            xb[p][c] = h[2 * p][c] + h[2 * p + 1][c];
        }
        __syncthreads();
        for (int o = t; o < hf * 640; o += 256) {
            int p = o / 640, c = o - p * 640;
            float a0 = 2.0f * bhh[c], a1 = 0.0f;
            const float* wc = Whh + c;
            const float* xp = xb[p];
            #pragma unroll 8
            for (int k = 0; k < 128; k += 2) {
                a0 = fmaf(xp[k],     wc[(size_t)k * 640],       a0);
                a1 = fmaf(xp[k + 1], wc[(size_t)(k + 1) * 640], a1);
            }
            sbuf[p][c] = a0 + a1;
        }
        __syncthreads();
        for (int i = t; i < hf * 128; i += 256) {
            int p = i >> 7, c = i & 127;
            float ig = sg(sbuf[p][c]);
            float lf = sg(sbuf[p][128 + c]);
            float rf = sg(sbuf[p][256 + c]);
            float og = sg(sbuf[p][384 + c]);
            float gg = th(sbuf[p][512 + c]);
            float cv = ig * gg + lf * h[2 * p][c] + rf * h[2 * p + 1][c];
            xb[p][c] = og * th(cv);          // stash (h still live)
        }
        __syncthreads();
        for (int i = t; i < hf * 128; i += 256)
            h[i >> 7][i & 127] = xb[i >> 7][i & 127];
        __syncthreads();
    }
    if (t < 128) out[(size_t)b * 128 + t] = h[0][t];
}

// ---------------------------------------------------------------------------
extern "C" void kernel_launch(void* const* d_in, const int* in_sizes, int n_in,
                              void* d_out, int out_size)
{
    const int*   wid = (const int*)  d_in[0];   // (B, L)
    const float* emb = (const float*)d_in[1];   // (V, DW)
    const float* Wwh = (const float*)d_in[2];   // (DW, H)
    const float* Whh = (const float*)d_in[3];   // (H, 5H)
    const float* bhh = (const float*)d_in[4];   // (5H,)
    float* out = (float*)d_out;                 // (B, 1, H)

    float *h0, *h1;
    __nv_bfloat16 *xh0, *xl0, *xh1, *xl1;
    cudaGetSymbolAddress((void**)&h0, g_h0);
    cudaGetSymbolAddress((void**)&h1, g_h1);
    cudaGetSymbolAddress((void**)&xh0, g_xhi0);
    cudaGetSymbolAddress((void**)&xl0, g_xlo0);
    cudaGetSymbolAddress((void**)&xh1, g_xhi1);
    cudaGetSymbolAddress((void**)&xl1, g_xlo1);

    cudaFuncSetAttribute(tree_mma,  cudaFuncAttributeMaxDynamicSharedMemorySize, TS_TOTAL);
    cudaFuncSetAttribute(embed_mma, cudaFuncAttributeMaxDynamicSharedMemorySize, ES_TOTAL);

    prep_weights<<<(4 * 160 * 128 + 128 * 128 + 255) / 256, 256>>>(Whh, Wwh);

    // Phase 1: gather-GEMM -> h0 (+ level-0 x pre-split into x buffer 0)
    embed_mma<<<(BB * LL) / 128, 512, ES_TOTAL>>>(wid, emb, h0);

    // Phase 2: mma levels n=2048..32; x double-buffered (race-free)
    const float* cur = h0;
    float* alt = h1;
    int xb = 0;
    for (int n = LL; n >= 32; n >>= 1) {
        int halfn = n >> 1;
        int P = BB * halfn;
        dim3 grid(P / 128, 4);
        const __nv_bfloat16* xih = xb ? xh1 : xh0;
        const __nv_bfloat16* xil = xb ? xl1 : xl0;
        __nv_bfloat16* xoh = xb ? xh0 : xh1;
        __nv_bfloat16* xol = xb ? xl0 : xl1;
        tree_mma<<<grid, 512, TS_TOTAL>>>(cur, alt, bhh, xih, xil, xoh, xol,
                                          P, (n > 32) ? 1 : 0);
        float* tmp = alt; alt = (float*)cur; cur = tmp;
        xb ^= 1;
    }

    // Phase 3: fused tail n=16..2 -> out
    tree_tail<<<BB, 256>>>(cur, out, Whh, bhh);
}

// round 11
// speedup vs baseline: 1.2094x; 1.2094x over previous
#include <cuda_runtime.h>
#include <cuda_bf16.h>
#include <cstdint>

// ---------------------------------------------------------------------------
// BinaryTreeLSTM  (B=64, L=2048, H=DW=128, V=100000) — mma.sync split-bf16
//
// Phase 1:  h0 = emb[word_ids] @ W_wh        (M=131072, K=128, N=128)
// Tree x11: s = (hl+hr) @ W_hh + 2*b_hh      (M=pairs,  K=128, N=640) ; gates
//
// Split-bf16: x = x_hi + x_lo, W = W_hi + W_lo
//   s ~= x_hi@W_hi + x_hi@W_lo + x_lo@W_hi   (3 bf16 passes, fp32 accum)
// W_hh column-reordered: tile tt (N=160) = cols tt*32..+31 of ALL 5 gates.
// R11: drop tree_tail (its per-CTA L2 W-streaming cost ~100us >> 4 small mma
// launches); tree_mma runs n=2048..2 with ceil-div grid + P guards; cp.async
// staging for W and X tiles. Pre-split x stays double-buffered (race-free).
// ---------------------------------------------------------------------------

#define BB 64
#define LL 2048
#define HH 128
#define MAXP (BB * LL / 2)

__device__ float g_h0[BB * LL * HH];             // 67 MB
__device__ float g_h1[MAXP * HH];                // 33.5 MB
__device__ __nv_bfloat16 g_xhi0[MAXP * HH];      // x ping-pong buffers
__device__ __nv_bfloat16 g_xlo0[MAXP * HH];
__device__ __nv_bfloat16 g_xhi1[MAXP * HH / 2];
__device__ __nv_bfloat16 g_xlo1[MAXP * HH / 2];
__device__ __nv_bfloat16 g_WrHi[4 * 160 * 128];  // reordered W_hh^T hi
__device__ __nv_bfloat16 g_WrLo[4 * 160 * 128];  // reordered W_hh^T lo
__device__ __nv_bfloat16 g_WtHi[128 * 128];      // W_wh^T hi
__device__ __nv_bfloat16 g_WtLo[128 * 128];      // W_wh^T lo

// ---------------------------------------------------------------- helpers
static __device__ __forceinline__ uint32_t smem_u32(const void* p) {
    uint32_t a;
    asm("{ .reg .u64 t; cvta.to.shared.u64 t, %1; cvt.u32.u64 %0, t; }"
        : "=r"(a) : "l"(p));
    return a;
}
// XOR-swizzled byte offset: rows of 256B, 16B chunks permuted by (row&7)
static __device__ __forceinline__ uint32_t swz(int row, int kb) {
    return (uint32_t)(row * 256 + (kb ^ ((row & 7) << 4)));
}
static __device__ __forceinline__ void cpa16(uint32_t dst, const void* src) {
    asm volatile("cp.async.ca.shared.global [%0], [%1], 16;"
                 :: "r"(dst), "l"(src) : "memory");
}
#define CPA_COMMIT() asm volatile("cp.async.commit_group;" ::: "memory")
#define CPA_WAIT()   asm volatile("cp.async.wait_group 0;" ::: "memory")

static __device__ __forceinline__ void ldmx4(uint32_t* r, uint32_t a) {
    asm volatile("ldmatrix.sync.aligned.m8n8.x4.shared.b16 {%0,%1,%2,%3}, [%4];"
                 : "=r"(r[0]), "=r"(r[1]), "=r"(r[2]), "=r"(r[3]) : "r"(a));
}
static __device__ __forceinline__ void ldmx2(uint32_t* r, uint32_t a) {
    asm volatile("ldmatrix.sync.aligned.m8n8.x2.shared.b16 {%0,%1}, [%2];"
                 : "=r"(r[0]), "=r"(r[1]) : "r"(a));
}
static __device__ __forceinline__ void mma_bf16(float* d, const uint32_t* a,
                                                const uint32_t* b) {
    asm volatile(
        "mma.sync.aligned.m16n8k16.row.col.f32.bf16.bf16.f32 "
        "{%0,%1,%2,%3}, {%4,%5,%6,%7}, {%8,%9}, {%0,%1,%2,%3};"
        : "+f"(d[0]), "+f"(d[1]), "+f"(d[2]), "+f"(d[3])
        : "r"(a[0]), "r"(a[1]), "r"(a[2]), "r"(a[3]), "r"(b[0]), "r"(b[1]));
}
static __device__ __forceinline__ void split_bf16(float x, unsigned short& h,
                                                  unsigned short& l) {
    __nv_bfloat16 hi = __float2bfloat16(x);
    __nv_bfloat16 lo = __float2bfloat16(x - __bfloat162float(hi));
    h = __bfloat16_as_ushort(hi);
    l = __bfloat16_as_ushort(lo);
}
static __device__ __forceinline__ float sg(float x) {
    return __fdividef(1.0f, 1.0f + __expf(-x));
}
static __device__ __forceinline__ float th(float x) {
    return __fdividef(2.0f, 1.0f + __expf(-2.0f * x)) - 1.0f;
}

// ---------------------------------------------------------------- weight prep
__global__ void prep_weights(const float* __restrict__ Whh,
                             const float* __restrict__ Wwh) {
    int idx = blockIdx.x * 256 + threadIdx.x;
    if (idx < 4 * 160 * 128) {
        int tt = idx / (160 * 128);
        int rem = idx - tt * 160 * 128;
        int row = rem >> 7, k = rem & 127;     // row = g*32+cc
        int g = row >> 5, cc = row & 31;
        float w = Whh[(size_t)k * 640 + g * 128 + tt * 32 + cc];
        unsigned short h, l; split_bf16(w, h, l);
        g_WrHi[idx] = __ushort_as_bfloat16(h);
        g_WrLo[idx] = __ushort_as_bfloat16(l);
    } else if (idx < 4 * 160 * 128 + 128 * 128) {
        int j = idx - 4 * 160 * 128;
        int n = j >> 7, k = j & 127;
        float w = Wwh[(size_t)k * 128 + n];
        unsigned short h, l; split_bf16(w, h, l);
        g_WtHi[j] = __ushort_as_bfloat16(h);
        g_WtLo[j] = __ushort_as_bfloat16(l);
    }
}

// ---------------------------------------------------------------- tree GEMM
// 512 threads, 16 warps as 4(M) x 4(N); warp tile 32 rows x 40 cols.
// smem: Xhi 32KB | Xlo 32KB | Whi 40KB | Wlo 40KB = 144KB; S reuses (82KB)
#define TS_XHI 0
#define TS_XLO 32768
#define TS_WHI 65536
#define TS_WLO (65536 + 40960)
#define TS_TOTAL (65536 + 81920)
#define SST 164   // S row stride in floats (164 % 32 == 4: conflict-free)

__global__ void __launch_bounds__(512)
tree_mma(const float* __restrict__ hin, float* __restrict__ hout,
         const float* __restrict__ bhh,
         const __nv_bfloat16* __restrict__ xin_hi,
         const __nv_bfloat16* __restrict__ xin_lo,
         __nv_bfloat16* __restrict__ xout_hi,
         __nv_bfloat16* __restrict__ xout_lo,
         int P, int writeX)
{
    extern __shared__ char smem[];
    const uint32_t sb = smem_u32(smem);
    const int t = threadIdx.x, wid = t >> 5, lane = t & 31;
    const int Mbase = blockIdx.x * 128;
    const int tt = blockIdx.y;

    // stage W tile (160 x 128 bf16, hi+lo) via cp.async
    {
        const uint4* sH = (const uint4*)(g_WrHi + tt * 160 * 128);
        const uint4* sL = (const uint4*)(g_WrLo + tt * 160 * 128);
        #pragma unroll
        for (int i = t; i < 2560; i += 512) {
            int row = i >> 4;
            uint32_t off = swz(row, (i & 15) << 4);
            cpa16(sb + TS_WHI + off, sH + i);
            cpa16(sb + TS_WLO + off, sL + i);
        }
    }
    // stage X tile: pre-split bf16 hi/lo straight from global via cp.async
    // (rows >= P read in-bounds garbage from the x buffer; epilogue guards)
    {
        #pragma unroll
        for (int i = t; i < 2048; i += 512) {
            int row = i >> 4;
            size_t gi = (size_t)(Mbase + row) * 16 + (i & 15);
            uint32_t off = swz(row, (i & 15) << 4);
            cpa16(sb + TS_XHI + off, (const uint4*)xin_hi + gi);
            cpa16(sb + TS_XLO + off, (const uint4*)xin_lo + gi);
        }
    }
    CPA_COMMIT();
    CPA_WAIT();
    __syncthreads();

    // warp tile: (wid>>2) of 4 M-tiles (32 rows), (wid&3) of 4 N-tiles (40 cols)
    const int mw = (wid >> 2) * 32, nw = (wid & 3) * 40;
    float acc[2][5][4];
    #pragma unroll
    for (int mi = 0; mi < 2; mi++)
        #pragma unroll
        for (int nj = 0; nj < 5; nj++)
            #pragma unroll
            for (int r = 0; r < 4; r++) acc[mi][nj][r] = 0.0f;

    const int la = lane & 15;
    const int arow_off = mw + la;          // + mi*16
    const int akb_off = (lane >> 4) * 16;  // + kstep*32
    // paired-B x4 mapping: matrices [nj k0, nj k1, nj+1 k0, nj+1 k1]
    const int b4row = nw + ((lane >> 4) & 1) * 8 + (lane & 7);
    const int b4kb = ((lane >> 3) & 1) * 16;
    // single-B x2 mapping (nj = 4)
    const int b2row = nw + 32 + (la & 7);
    const int b2kb = (la >> 3) * 16;

    #pragma unroll
    for (int ks = 0; ks < 8; ks++) {
        uint32_t ah[2][4], al[2][4];
        #pragma unroll
        for (int mi = 0; mi < 2; mi++) {
            int row = arow_off + mi * 16;
            uint32_t off = swz(row, akb_off + ks * 32);
            ldmx4(ah[mi], sb + TS_XHI + off);
            ldmx4(al[mi], sb + TS_XLO + off);
        }
        uint32_t bh[10], bl[10];   // [nj*2 + khalf]
        #pragma unroll
        for (int njp = 0; njp < 2; njp++) {
            uint32_t off = swz(b4row + njp * 16, b4kb + ks * 32);
            ldmx4(bh + njp * 4, sb + TS_WHI + off);
            ldmx4(bl + njp * 4, sb + TS_WLO + off);
        }
        {
            uint32_t off = swz(b2row, b2kb + ks * 32);
            ldmx2(bh + 8, sb + TS_WHI + off);
            ldmx2(bl + 8, sb + TS_WLO + off);
        }
        #pragma unroll
        for (int nj = 0; nj < 5; nj++) {
            #pragma unroll
            for (int mi = 0; mi < 2; mi++) {
                mma_bf16(acc[mi][nj], ah[mi], bh + nj * 2);   // hi*hi
                mma_bf16(acc[mi][nj], ah[mi], bl + nj * 2);   // hi*lo
                mma_bf16(acc[mi][nj], al[mi], bh + nj * 2);   // lo*hi
            }
        }
    }
    __syncthreads();   // staging no longer needed; reuse smem for S

    // scatter S (rows 128 x cols 160, fp32) to smem
    float* S = (float*)smem;
    {
        const int r0 = mw + (lane >> 2);
        const int c0 = nw + (lane & 3) * 2;
        #pragma unroll
        for (int mi = 0; mi < 2; mi++)
            #pragma unroll
            for (int nj = 0; nj < 5; nj++) {
                int row = r0 + mi * 16, col = c0 + nj * 8;
                *(float2*)&S[row * SST + col] =
                    make_float2(acc[mi][nj][0], acc[mi][nj][1]);
                *(float2*)&S[(row + 8) * SST + col] =
                    make_float2(acc[mi][nj][2], acc[mi][nj][3]);
            }
    }
    __syncthreads();

    // fused gate epilogue: thread -> col cc=lane, rows wid*8..+7 (4 pairs)
    {
        const int cb = tt * 32;
        const int cc = lane;
        float b0 = 2.0f * bhh[0 * HH + cb + cc];
        float b1 = 2.0f * bhh[1 * HH + cb + cc];
        float b2 = 2.0f * bhh[2 * HH + cb + cc];
        float b3 = 2.0f * bhh[3 * HH + cb + cc];
        float b4 = 2.0f * bhh[4 * HH + cb + cc];
        #pragma unroll
        for (int rr = 0; rr < 8; rr += 2) {
            int p0 = Mbase + wid * 8 + rr;
            if (p0 + 1 >= P && p0 >= P) continue;   // whole pair out of range
            float hv[2];
            #pragma unroll
            for (int e = 0; e < 2; e++) {
                int row = wid * 8 + rr + e;
                int p = Mbase + row;
                const float* Sr = S + row * SST + cc;
                float ig = sg(Sr[0]   + b0);
                float lf = sg(Sr[32]  + b1);
                float rf = sg(Sr[64]  + b2);
                float og = sg(Sr[96]  + b3);
                float gg = th(Sr[128] + b4);
                float hl = hin[(size_t)(2 * p) * HH + cb + cc];
                float hr = hin[(size_t)(2 * p) * HH + HH + cb + cc];
                float c = ig * gg + lf * hl + rf * hr;
                hv[e] = og * th(c);
                if (p < P) hout[(size_t)p * HH + cb + cc] = hv[e];
            }
            if (writeX && p0 + 1 < P) {  // pre-split next level's x (other buf)
                unsigned short xh, xl;
                split_bf16(hv[0] + hv[1], xh, xl);
                size_t p2 = (size_t)(p0 >> 1) * HH + cb + cc;
                xout_hi[p2] = __ushort_as_bfloat16(xh);
                xout_lo[p2] = __ushort_as_bfloat16(xl);
            }
        }
    }
}

// ---------------------------------------------------------------- embed GEMM
// 512 threads, 16 warps as 4(M) x 4(N); warp tile 32 rows x 32 cols.
// smem: Xhi 32KB | Xlo 32KB | Whi 32KB | Wlo 32KB = 128KB; S reuses (66KB)
#define ES_XHI 0
#define ES_XLO 32768
#define ES_WHI 65536
#define ES_WLO 98304
#define ES_TOTAL 131072
#define EST 132   // S row stride (132 % 32 == 4)

__global__ void __launch_bounds__(512)
embed_mma(const int* __restrict__ wids_g, const float* __restrict__ emb,
          float* __restrict__ hout)
{
    extern __shared__ char smem[];
    __shared__ int wids_s[128];
    const uint32_t sb = smem_u32(smem);
    const int t = threadIdx.x, wid = t >> 5, lane = t & 31;
    const int Mbase = blockIdx.x * 128;

    if (t < 128) wids_s[t] = wids_g[Mbase + t];

    // stage W (128 x 128 bf16, hi+lo) via cp.async
    {
        const uint4* sH = (const uint4*)g_WtHi;
        const uint4* sL = (const uint4*)g_WtLo;
        #pragma unroll
        for (int i = t; i < 2048; i += 512) {
            int row = i >> 4;
            uint32_t off = swz(row, (i & 15) << 4);
            cpa16(sb + ES_WHI + off, sH + i);
            cpa16(sb + ES_WLO + off, sL + i);
        }
    }
    CPA_COMMIT();
    __syncthreads();   // wids_s ready

    // gather + split E rows (compute path: regular loads)
    {
        #pragma unroll
        for (int i = t; i < 2048; i += 512) {
            int row = i >> 4, kc = (i & 15) * 8;      // 8 floats
            const float4* e4 =
                (const float4*)(emb + (size_t)wids_s[row] * 128 + kc);
            float4 a = e4[0], b = e4[1];
            ushort4 vh0, vl0, vh1, vl1;
            split_bf16(a.x, vh0.x, vl0.x); split_bf16(a.y, vh0.y, vl0.y);
            split_bf16(a.z, vh0.z, vl0.z); split_bf16(a.w, vh0.w, vl0.w);
            split_bf16(b.x, vh1.x, vl1.x); split_bf16(b.y, vh1.y, vl1.y);
            split_bf16(b.z, vh1.z, vl1.z); split_bf16(b.w, vh1.w, vl1.w);
            uint32_t off = swz(row, (i & 15) << 4);
            *(ushort4*)(smem + ES_XHI + off) = vh0;
            *(ushort4*)(smem + ES_XHI + off + 8) = vh1;
            *(ushort4*)(smem + ES_XLO + off) = vl0;
            *(ushort4*)(smem + ES_XLO + off + 8) = vl1;
        }
    }
    CPA_WAIT();
    __syncthreads();

    // warp tile: (wid>>2) of 4 M-tiles (32 rows), (wid&3) of 4 N-tiles (32 cols)
    const int mw = (wid >> 2) * 32, nw = (wid & 3) * 32;
    float acc[2][4][4];
    #pragma unroll
    for (int mi = 0; mi < 2; mi++)
        #pragma unroll
        for (int nj = 0; nj < 4; nj++)
            #pragma unroll
            for (int r = 0; r < 4; r++) acc[mi][nj][r] = 0.0f;

    const int la = lane & 15;
    const int arow_off = mw + la;
    const int akb_off = (lane >> 4) * 16;
    const int b4row = nw + ((lane >> 4) & 1) * 8 + (lane & 7);
    const int b4kb = ((lane >> 3) & 1) * 16;

    #pragma unroll
    for (int ks = 0; ks < 8; ks++) {
        uint32_t ah[2][4], al[2][4];
        #pragma unroll
        for (int mi = 0; mi < 2; mi++) {
            int row = arow_off + mi * 16;
            uint32_t off = swz(row, akb_off + ks * 32);
            ldmx4(ah[mi], sb + ES_XHI + off);
            ldmx4(al[mi], sb + ES_XLO + off);
        }
        uint32_t bh[8], bl[8];
        #pragma unroll
        for (int njp = 0; njp < 2; njp++) {
            uint32_t off = swz(b4row + njp * 16, b4kb + ks * 32);
            ldmx4(bh + njp * 4, sb + ES_WHI + off);
            ldmx4(bl + njp * 4, sb + ES_WLO + off);
        }
        #pragma unroll
        for (int nj = 0; nj < 4; nj++) {
            #pragma unroll
            for (int mi = 0; mi < 2; mi++) {
                mma_bf16(acc[mi][nj], ah[mi], bh + nj * 2);
                mma_bf16(acc[mi][nj], ah[mi], bl + nj * 2);
                mma_bf16(acc[mi][nj], al[mi], bh + nj * 2);
            }
        }
    }
    __syncthreads();

    // S -> smem
    float* S = (float*)smem;
    {
        const int r0 = mw + (lane >> 2);
        const int c0 = nw + (lane & 3) * 2;
        #pragma unroll
        for (int mi = 0; mi < 2; mi++)
            #pragma unroll
            for (int nj = 0; nj < 4; nj++) {
                int row = r0 + mi * 16, col = c0 + nj * 8;
                *(float2*)&S[row * EST + col] =
                    make_float2(acc[mi][nj][0], acc[mi][nj][1]);
                *(float2*)&S[(row + 8) * EST + col] =
                    make_float2(acc[mi][nj][2], acc[mi][nj][3]);
            }
    }
    __syncthreads();
    // coalesced h0 stores
    {
        #pragma unroll
        for (int i = t; i < 4096; i += 512) {       // 128 rows x 32 float4
            int row = i >> 5, c4 = i & 31;
            float4 v = *(const float4*)&S[row * EST + c4 * 4];
            ((float4*)hout)[(size_t)(Mbase + row) * 32 + c4] = v;
        }
    }
    // pre-split level-0 x into buffer 0: pairs are tile-internal
    {
        #pragma unroll
        for (int i = t; i < 1024; i += 512) {       // 64 pair-rows x 16 chunks
            int r2 = i >> 4, ch = i & 15;
            const float* s0 = &S[(2 * r2) * EST + ch * 8];
            const float* s1 = &S[(2 * r2 + 1) * EST + ch * 8];
            ushort4 vh0, vl0, vh1, vl1;
            split_bf16(s0[0] + s1[0], vh0.x, vl0.x);
            split_bf16(s0[1] + s1[1], vh0.y, vl0.y);
            split_bf16(s0[2] + s1[2], vh0.z, vl0.z);
            split_bf16(s0[3] + s1[3], vh0.w, vl0.w);
            split_bf16(s0[4] + s1[4], vh1.x, vl1.x);
            split_bf16(s0[5] + s1[5], vh1.y, vl1.y);
            split_bf16(s0[6] + s1[6], vh1.z, vl1.z);
            split_bf16(s0[7] + s1[7], vh1.w, vl1.w);
            size_t eb = (size_t)((Mbase >> 1) + r2) * HH + ch * 8;
            *(ushort4*)(g_xhi0 + eb) = vh0;
            *(ushort4*)(g_xhi0 + eb + 4) = vh1;
            *(ushort4*)(g_xlo0 + eb) = vl0;
            *(ushort4*)(g_xlo0 + eb + 4) = vl1;
        }
    }
}

// ---------------------------------------------------------------------------
extern "C" void kernel_launch(void* const* d_in, const int* in_sizes, int n_in,
                              void* d_out, int out_size)
{
    const int*   wid = (const int*)  d_in[0];   // (B, L)
    const float* emb = (const float*)d_in[1];   // (V, DW)
    const float* Wwh = (const float*)d_in[2];   // (DW, H)
    const float* Whh = (const float*)d_in[3];   // (H, 5H)
    const float* bhh = (const float*)d_in[4];   // (5H,)
    float* out = (float*)d_out;                 // (B, 1, H)

    float *h0, *h1;
    __nv_bfloat16 *xh0, *xl0, *xh1, *xl1;
    cudaGetSymbolAddress((void**)&h0, g_h0);
    cudaGetSymbolAddress((void**)&h1, g_h1);
    cudaGetSymbolAddress((void**)&xh0, g_xhi0);
    cudaGetSymbolAddress((void**)&xl0, g_xlo0);
    cudaGetSymbolAddress((void**)&xh1, g_xhi1);
    cudaGetSymbolAddress((void**)&xl1, g_xlo1);

    cudaFuncSetAttribute(tree_mma,  cudaFuncAttributeMaxDynamicSharedMemorySize, TS_TOTAL);
    cudaFuncSetAttribute(embed_mma, cudaFuncAttributeMaxDynamicSharedMemorySize, ES_TOTAL);

    prep_weights<<<(4 * 160 * 128 + 128 * 128 + 255) / 256, 256>>>(Whh, Wwh);

    // Phase 1: gather-GEMM -> h0 (+ level-0 x pre-split into x buffer 0)
    embed_mma<<<(BB * LL) / 128, 512, ES_TOTAL>>>(wid, emb, h0);

    // Phase 2: mma levels n=2048..2; x double-buffered (race-free)
    const float* cur = h0;
    float* alt = h1;
    int xb = 0;
    for (int n = LL; n >= 2; n >>= 1) {
        int halfn = n >> 1;
        int P = BB * halfn;
        dim3 grid((P + 127) / 128, 4);
        const __nv_bfloat16* xih = xb ? xh1 : xh0;
        const __nv_bfloat16* xil = xb ? xl1 : xl0;
        __nv_bfloat16* xoh = xb ? xh0 : xh1;
        __nv_bfloat16* xol = xb ? xl0 : xl1;
        float* o = (n == 2) ? out : alt;
        tree_mma<<<grid, 512, TS_TOTAL>>>(cur, o, bhh, xih, xil, xoh, xol,
                                          P, (n > 2) ? 1 : 0);
        float* tmp = alt; alt = (float*)cur; cur = tmp;
        xb ^= 1;
    }
}